// round 5
// baseline (speedup 1.0000x reference)
#include <cuda_runtime.h>
#include <cuda_bf16.h>
#include <cstdint>

#define N_NODES 100000
#define N_EDGES 1600000
#define D_FEAT  50
#define D2      25              // float2 elements per row
#define KITER   3

static __device__ __constant__ float TAU = 0.1f / 1.8f;   // gamma * lambda

// ---------------- scratch (device globals; no allocation allowed) ----------
__device__ float  g_outdeg[N_NODES];
__device__ float  g_indeg [N_NODES];
__device__ float  g_ws    [N_NODES];         // self-loop weight
__device__ int    g_cnt   [N_NODES];         // in-degree (edge count, no self)
__device__ int    g_start [N_NODES];         // CSR row start
__device__ int    g_cursor[N_NODES];
__device__ int    g_bsum  [128];
__device__ int    g_boff  [128];
__device__ float2 g_edge  [N_EDGES];         // {src (bits), w}
__device__ float  g_x1    [N_NODES * D_FEAT];
__device__ float  g_x2    [N_NODES * D_FEAT];

// ---------------- build phase ----------------------------------------------
__global__ void k_init() {
    int i = blockIdx.x * blockDim.x + threadIdx.x;
    if (i >= N_NODES) return;
    g_outdeg[i] = 1.0f;          // self-loop weight 1 pre-added
    g_indeg [i] = 1.0f;
    g_cnt   [i] = 0;
}

__global__ void k_deg(const float* __restrict__ ew,
                      const int* __restrict__ src,
                      const int* __restrict__ dst) {
    int e = blockIdx.x * blockDim.x + threadIdx.x;
    if (e >= N_EDGES) return;
    float w = ew[e];
    int s = src[e], d = dst[e];
    atomicAdd(&g_outdeg[s], w);
    atomicAdd(&g_indeg [d], w);
    atomicAdd(&g_cnt   [d], 1);
}

// block-level exclusive scan of g_cnt (1024 elems / block)
__global__ void k_scan1() {
    __shared__ int sh[1024];
    int i = blockIdx.x * 1024 + threadIdx.x;
    int v = (i < N_NODES) ? g_cnt[i] : 0;
    sh[threadIdx.x] = v;
    __syncthreads();
    for (int off = 1; off < 1024; off <<= 1) {
        int t = (threadIdx.x >= off) ? sh[threadIdx.x - off] : 0;
        __syncthreads();
        sh[threadIdx.x] += t;
        __syncthreads();
    }
    if (i < N_NODES) g_start[i] = sh[threadIdx.x] - v;   // exclusive
    if (threadIdx.x == 1023) g_bsum[blockIdx.x] = sh[1023];
}

__global__ void k_scan2(int nblk) {   // tiny serial scan of block sums
    if (threadIdx.x == 0 && blockIdx.x == 0) {
        int acc = 0;
        for (int b = 0; b < nblk; b++) { g_boff[b] = acc; acc += g_bsum[b]; }
    }
}

__global__ void k_scan3() {
    int i = blockIdx.x * blockDim.x + threadIdx.x;
    if (i >= N_NODES) return;
    int st = g_start[i] + g_boff[i >> 10];
    g_start [i] = st;
    g_cursor[i] = st;
    g_ws[i] = rsqrtf(g_outdeg[i] * g_indeg[i]);
}

__global__ void k_scatter(const float* __restrict__ ew,
                          const int* __restrict__ src,
                          const int* __restrict__ dst) {
    int e = blockIdx.x * blockDim.x + threadIdx.x;
    if (e >= N_EDGES) return;
    int s = src[e], d = dst[e];
    float w = ew[e] * rsqrtf(g_outdeg[s]) * rsqrtf(g_indeg[d]);
    int pos = atomicAdd(&g_cursor[d], 1);
    g_edge[pos] = make_float2(__int_as_float(s), w);
}

// ---------------- fused SpMM + proximal: warp per dst node ------------------
__global__ void __launch_bounds__(256)
k_spmm_prox(const float* __restrict__ xin,
            const float* __restrict__ feat,
            float* __restrict__ xout) {
    int warp = (blockIdx.x * blockDim.x + threadIdx.x) >> 5;
    int lane = threadIdx.x & 31;
    if (warp >= N_NODES) return;
    const int i = warp;

    const int   start = g_start[i];
    const int   cnt   = g_cnt[i];
    const float ws    = g_ws[i];
    const bool  act   = lane < D2;

    const float2* __restrict__ xin2  = reinterpret_cast<const float2*>(xin);
    const float2* __restrict__ feat2 = reinterpret_cast<const float2*>(feat);

    float2 acc = make_float2(0.f, 0.f);
    if (act) {
        float2 xv = xin2[i * D2 + lane];
        acc.x = ws * xv.x;
        acc.y = ws * xv.y;
    }

    const float2* __restrict__ ep = g_edge + start;
    int e = 0;
    // 2-edge software pipeline: both meta loads issue before dependent row loads
    for (; e + 1 < cnt; e += 2) {
        float2 m0 = ep[e];
        float2 m1 = ep[e + 1];
        int s0 = __float_as_int(m0.x);
        int s1 = __float_as_int(m1.x);
        if (act) {
            float2 v0 = xin2[s0 * D2 + lane];
            float2 v1 = xin2[s1 * D2 + lane];
            acc.x = fmaf(m0.y, v0.x, acc.x);
            acc.y = fmaf(m0.y, v0.y, acc.y);
            acc.x = fmaf(m1.y, v1.x, acc.x);
            acc.y = fmaf(m1.y, v1.y, acc.y);
        }
    }
    if (e < cnt) {
        float2 m0 = ep[e];
        int s0 = __float_as_int(m0.x);
        if (act) {
            float2 v0 = xin2[s0 * D2 + lane];
            acc.x = fmaf(m0.y, v0.x, acc.x);
            acc.y = fmaf(m0.y, v0.y, acc.y);
        }
    }

    // proximal L2,1 on (agg - feat)
    float2 f = act ? feat2[i * D2 + lane] : make_float2(0.f, 0.f);
    float dx = acc.x - f.x;
    float dy = acc.y - f.y;
    float sq = act ? (dx * dx + dy * dy) : 0.f;
    #pragma unroll
    for (int o = 16; o; o >>= 1)
        sq += __shfl_xor_sync(0xffffffffu, sq, o);
    float nrm = sqrtf(sq);
    float scale = (nrm > 0.f) ? fmaxf(nrm - TAU, 0.f) / nrm : 0.f;

    if (act) {
        float2 o;
        o.x = f.x + scale * dx;
        o.y = f.y + scale * dy;
        reinterpret_cast<float2*>(xout)[i * D2 + lane] = o;
    }
}

// ---------------- launch ----------------------------------------------------
extern "C" void kernel_launch(void* const* d_in, const int* in_sizes, int n_in,
                              void* d_out, int out_size) {
    const float* feat = (const float*)d_in[0];
    const float* ew   = (const float*)d_in[1];
    const int*   src  = (const int*)d_in[2];
    const int*   dst  = (const int*)d_in[3];
    float*       out  = (float*)d_out;

    const int nodeBlocks = (N_NODES + 255) / 256;
    const int edgeBlocks = (N_EDGES + 255) / 256;
    const int scanBlocks = (N_NODES + 1023) / 1024;   // 98

    k_init   <<<nodeBlocks, 256>>>();
    k_deg    <<<edgeBlocks, 256>>>(ew, src, dst);
    k_scan1  <<<scanBlocks, 1024>>>();
    k_scan2  <<<1, 32>>>(scanBlocks);
    k_scan3  <<<nodeBlocks, 256>>>();
    k_scatter<<<edgeBlocks, 256>>>(ew, src, dst);

    // resolve device-global addresses (compile-time symbols, no API calls)
    float* x1;
    float* x2;
    cudaGetSymbolAddress((void**)&x1, g_x1);
    cudaGetSymbolAddress((void**)&x2, g_x2);

    const int spmmBlocks = (N_NODES * 32 + 255) / 256;   // warp per node
    k_spmm_prox<<<spmmBlocks, 256>>>(feat, feat, x1);
    k_spmm_prox<<<spmmBlocks, 256>>>(x1,   feat, x2);
    k_spmm_prox<<<spmmBlocks, 256>>>(x2,   feat, out);
}